// round 12
// baseline (speedup 1.0000x reference)
#include <cuda_runtime.h>
#include <cuda_fp16.h>
#include <math.h>
#include <stdint.h>

// Problem constants
#define BATCH 256
#define DIM   1024
#define L_IM  37
#define L_S   33
#define LI    36
#define LS    30
#define MARGIN 0.2f

#define MROWS  (BATCH*LI)     // 9216
#define NCOLS  (BATCH*LS)     // 7680

// ---- device scratch (allocation-free rule) ----
__device__ __half g_A[(size_t)MROWS * DIM];
__device__ __half g_B[(size_t)NCOLS * DIM];
__device__ float  g_colmax[(size_t)BATCH * NCOLS];
__device__ float  g_scores[BATCH * BATCH];
__device__ float  g_red[BATCH];           // per-row cost_s max
__device__ int    g_cnt = 0;

__device__ __forceinline__ uint32_t s2u(const void* p) {
    return (uint32_t)__cvta_generic_to_shared(p);
}

// ============================================================================
// Kernel 1: L2-normalize + slice + fp16 convert (both tensors, one launch).
// ============================================================================
__global__ void norm_kernel(const float* __restrict__ im_in, const float* __restrict__ s_in)
{
    int ob = blockIdx.x;
    int which = (ob >= MROWS);
    const float* in = which ? s_in : im_in;
    int Lin  = which ? L_S : L_IM;
    int Lout = which ? LS  : LI;
    if (which) ob -= MROWS;
    int b = ob / Lout;
    int i = ob % Lout;
    const float4* src = (const float4*)(in + ((size_t)b * Lin + i + 1) * DIM);
    float4 v = src[threadIdx.x];

    float ss = v.x*v.x + v.y*v.y + v.z*v.z + v.w*v.w;
    #pragma unroll
    for (int o = 16; o > 0; o >>= 1) ss += __shfl_down_sync(0xffffffffu, ss, o);

    __shared__ float warp_s[8];
    __shared__ float inv_s;
    if ((threadIdx.x & 31) == 0) warp_s[threadIdx.x >> 5] = ss;
    __syncthreads();
    if (threadIdx.x == 0) {
        float tot = 0.f;
        #pragma unroll
        for (int q = 0; q < 8; q++) tot += warp_s[q];
        inv_s = 1.0f / fmaxf(sqrtf(tot), 1e-12f);
    }
    __syncthreads();
    float inv = inv_s;

    __half2 h01 = __floats2half2_rn(v.x * inv, v.y * inv);
    __half2 h23 = __floats2half2_rn(v.z * inv, v.w * inv);
    __half* dst = (which ? g_B : g_A) + (size_t)ob * DIM + 4 * threadIdx.x;
    *(__half2*)(dst)     = h01;
    *(__half2*)(dst + 2) = h23;
}

// ============================================================================
// Kernel 2: fp16 mma.sync GEMM with FUSED masked max-over-regions epilogue.
//   (byte-identical to R11 best: 144x128x64, 192 thr, occ 2, 3-stage pipe)
// ============================================================================
#define BM 144
#define BN 128
#define BKH 64
#define STAGES 3
#define ROWB 128
#define STAGE_BYTES ((BM + BN) * ROWB)   // 34816
#define KTILES (DIM / BKH)               // 16
#define NTH 192
#define ESTR 132
#define SMEM_SZ (STAGES * STAGE_BYTES)   // 104448

__device__ __forceinline__ void cp16(uint32_t dst, const void* src) {
    asm volatile("cp.async.cg.shared.global [%0], [%1], 16;" :: "r"(dst), "l"(src));
}
__device__ __forceinline__ uint32_t swz(int row, int seg) {
    return (uint32_t)(row * ROWB + ((seg ^ (row & 7)) << 4));
}
#define LDSM4(r, addr) \
    asm volatile("ldmatrix.sync.aligned.m8n8.x4.shared.b16 {%0,%1,%2,%3}, [%4];" \
        : "=r"((r)[0]), "=r"((r)[1]), "=r"((r)[2]), "=r"((r)[3]) : "r"(addr))
#define HMMA(acc, a0, a1, a2, a3, b0, b1) \
    asm volatile("mma.sync.aligned.m16n8k16.row.col.f32.f16.f16.f32 " \
        "{%0,%1,%2,%3}, {%4,%5,%6,%7}, {%8,%9}, {%0,%1,%2,%3};" \
        : "+f"((acc)[0]), "+f"((acc)[1]), "+f"((acc)[2]), "+f"((acc)[3]) \
        : "r"(a0), "r"(a1), "r"(a2), "r"(a3), "r"(b0), "r"(b1))

__device__ __forceinline__ void load_stage(char* dsm, int slot, int m0, int n0, int kc, int t)
{
    char* As = dsm + slot * STAGE_BYTES;
    char* Bs = As + BM * ROWB;
    const __half* Agp = g_A + (size_t)m0 * DIM + kc * BKH;
    const __half* Bgp = g_B + (size_t)n0 * DIM + kc * BKH;
    #pragma unroll
    for (int i = 0; i < 6; i++) {
        int idx = t + i * NTH;
        int row = idx >> 3, seg = idx & 7;
        cp16(s2u(As + swz(row, seg)), Agp + (size_t)row * DIM + seg * 8);
    }
    #pragma unroll
    for (int i = 0; i < 6; i++) {
        int idx = t + i * NTH;
        if (idx < 1024) {
            int row = idx >> 3, seg = idx & 7;
            cp16(s2u(Bs + swz(row, seg)), Bgp + (size_t)row * DIM + seg * 8);
        }
    }
}

__global__ __launch_bounds__(NTH, 2) void gemm_kernel(const int* __restrict__ im_len)
{
    extern __shared__ __align__(128) char dsm[];
    const int t   = threadIdx.x;
    const int wid = t >> 5, lid = t & 31;
    const int warp_m = (wid % 3) * 48;
    const int warp_n = (wid / 3) * 64;
    const int m0 = blockIdx.y * BM;
    const int n0 = blockIdx.x * BN;

    float acc[3][8][4];
    #pragma unroll
    for (int mf = 0; mf < 3; mf++)
        #pragma unroll
        for (int nf = 0; nf < 8; nf++)
            #pragma unroll
            for (int q = 0; q < 4; q++) acc[mf][nf][q] = 0.f;

    #pragma unroll
    for (int s = 0; s < STAGES - 1; s++) {
        load_stage(dsm, s, m0, n0, s, t);
        asm volatile("cp.async.commit_group;");
    }

    int rowA[3], rswA[3];
    #pragma unroll
    for (int mf = 0; mf < 3; mf++) {
        rowA[mf] = warp_m + mf * 16 + (lid & 15);
        rswA[mf] = rowA[mf] & 7;
    }
    const int a_seg0 = (lid >> 4);
    const int b_row_base = warp_n + ((lid >> 4) & 1) * 8 + (lid & 7);
    const int b_seg0 = (lid >> 3) & 1;

    int slot = 0, lslot = STAGES - 1;
    for (int j = 0; j < KTILES; j++) {
        if (j < KTILES - 1) asm volatile("cp.async.wait_group 1;");
        else                asm volatile("cp.async.wait_group 0;");
        __syncthreads();

        int jl = j + STAGES - 1;
        if (jl < KTILES) {
            load_stage(dsm, lslot, m0, n0, jl, t);
            asm volatile("cp.async.commit_group;");
        }

        const uint32_t AsU = s2u(dsm) + slot * STAGE_BYTES;
        const uint32_t BsU = AsU + BM * ROWB;

        #pragma unroll
        for (int ks = 0; ks < 4; ks++) {
            uint32_t a[3][4];
            #pragma unroll
            for (int mf = 0; mf < 3; mf++)
                LDSM4(a[mf], AsU + rowA[mf] * ROWB
                             + (((a_seg0 + 2 * ks) ^ rswA[mf]) << 4));
            uint32_t bf[4][4];
            #pragma unroll
            for (int np = 0; np < 4; np++) {
                int row = b_row_base + np * 16;
                LDSM4(bf[np], BsU + row * ROWB
                              + (((b_seg0 + 2 * ks) ^ (row & 7)) << 4));
            }
            #pragma unroll
            for (int nf = 0; nf < 8; nf++) {
                uint32_t b0 = bf[nf >> 1][(nf & 1) * 2];
                uint32_t b1 = bf[nf >> 1][(nf & 1) * 2 + 1];
                #pragma unroll
                for (int mf = 0; mf < 3; mf++)
                    HMMA(acc[mf][nf], a[mf][0], a[mf][1], a[mf][2], a[mf][3], b0, b1);
            }
        }
        slot  = (slot  == STAGES - 1) ? 0 : slot + 1;
        lslot = (lslot == STAGES - 1) ? 0 : lslot + 1;
    }

    __syncthreads();
    float* etile = (float*)dsm;
    const int r0 = warp_m + (lid >> 2);
    const int c0 = warp_n + (lid & 3) * 2;
    #pragma unroll
    for (int mf = 0; mf < 3; mf++) {
        #pragma unroll
        for (int nf = 0; nf < 8; nf++) {
            int r = r0 + mf * 16;
            int c = c0 + nf * 8;
            etile[r * ESTR + c]           = acc[mf][nf][0];
            etile[r * ESTR + c + 1]       = acc[mf][nf][1];
            etile[(r + 8) * ESTR + c]     = acc[mf][nf][2];
            etile[(r + 8) * ESTR + c + 1] = acc[mf][nf][3];
        }
    }
    __syncthreads();

    const int bimg0 = blockIdx.y * 4;
    for (int idx = t; idx < 512; idx += NTH) {
        int img = idx >> 7, col = idx & 127;
        int iml = im_len[bimg0 + img] - 1;
        const float* colp = etile + img * 36 * ESTR + col;
        float m = -1e30f;
        for (int r = 0; r < iml; r++) m = fmaxf(m, colp[r * ESTR]);
        if (iml < LI) m = fmaxf(m, 0.f);
        g_colmax[(size_t)(bimg0 + img) * NCOLS + n0 + col] = m;
    }
}

// ============================================================================
// Kernel 3 (fused score + loss): block b computes scores row b AND the
// cost_s row-max (diag is local); last block (counter) computes cost_im
// column maxes with coalesced reads and the final sum.
// ============================================================================
__global__ __launch_bounds__(256) void scoreloss_kernel(const int* __restrict__ s_len,
                                                        float* __restrict__ out)
{
    __shared__ float row[NCOLS];           // colmax row b (30720 B)
    __shared__ float srow[BATCH];          // scores row b
    const int b = blockIdx.x, t = threadIdx.x;

    const float4* src = (const float4*)(g_colmax + (size_t)b * NCOLS);
    #pragma unroll
    for (int i = 0; i < 8; i++) {
        int idx = t + i * 256;
        if (idx < NCOLS / 4)
            *(float4*)(row + 4 * idx) = src[idx];
    }
    __syncthreads();

    int sl = s_len[t] - 3;
    if (sl > LS) sl = LS;
    if (sl < 0)  sl = 0;
    const float* p = row + t * LS;
    float sc = 0.f;
    for (int j = 0; j < sl; j++) sc += p[j];
    g_scores[b * BATCH + t] = sc;
    srow[t] = sc;
    __syncthreads();

    // cost_s row-max for row b (diag available locally)
    float d = srow[b];
    float v1 = (t != b) ? fmaxf(0.f, MARGIN + sc - d) : 0.f;
    #pragma unroll
    for (int o = 16; o > 0; o >>= 1)
        v1 = fmaxf(v1, __shfl_down_sync(0xffffffffu, v1, o));
    __shared__ float w1[8];
    if ((t & 31) == 0) w1[t >> 5] = v1;
    __syncthreads();

    __shared__ int is_last;
    if (t == 0) {
        float m1 = w1[0];
        #pragma unroll
        for (int q = 1; q < 8; q++) m1 = fmaxf(m1, w1[q]);
        g_red[b] = m1;
        __threadfence();
        is_last = (atomicAdd(&g_cnt, 1) == BATCH - 1);
    }
    __syncthreads();

    if (is_last) {
        // cost_im column max for column t (coalesced: row-major sweep)
        int c = t;
        float dc = g_scores[c * BATCH + c];
        float vm = 0.f;
        for (int r = 0; r < BATCH; r++) {
            float v = MARGIN + g_scores[r * BATCH + c] - dc;
            if (r != c) vm = fmaxf(vm, fmaxf(0.f, v));
        }
        __shared__ float sm[BATCH];
        sm[t] = g_red[t] + vm;
        __syncthreads();
        #pragma unroll
        for (int o = 128; o > 0; o >>= 1) {
            if (t < o) sm[t] += sm[t + o];
            __syncthreads();
        }
        if (t == 0) { out[0] = sm[0]; g_cnt = 0; }   // reset: graph-replay safe
    }
}

// ============================================================================
extern "C" void kernel_launch(void* const* d_in, const int* in_sizes, int n_in,
                              void* d_out, int out_size)
{
    const float* im_set = (const float*)d_in[0];
    const float* s_seq  = (const float*)d_in[1];
    const int*   im_len = (const int*)d_in[2];
    const int*   s_len  = (const int*)d_in[3];
    float* out = (float*)d_out;

    cudaFuncSetAttribute(gemm_kernel, cudaFuncAttributeMaxDynamicSharedMemorySize,
                         SMEM_SZ);

    norm_kernel<<<BATCH * LI + BATCH * LS, 256>>>(im_set, s_seq);

    dim3 grid(NCOLS / BN, MROWS / BM);   // (60, 64)
    gemm_kernel<<<grid, NTH, SMEM_SZ>>>(im_len);

    scoreloss_kernel<<<BATCH, 256>>>(s_len, out);
}

// round 13
// speedup vs baseline: 1.0337x; 1.0337x over previous
#include <cuda_runtime.h>
#include <cuda_fp16.h>
#include <math.h>
#include <stdint.h>

// Problem constants
#define BATCH 256
#define DIM   1024
#define L_IM  37
#define L_S   33
#define LI    36
#define LS    30
#define MARGIN 0.2f

#define MROWS  (BATCH*LI)     // 9216
#define NCOLS  (BATCH*LS)     // 7680
#define TROWS  (MROWS + BATCH*LS)   // 16896 total output rows

// ---- device scratch (allocation-free rule) ----
__device__ __half g_A[(size_t)MROWS * DIM];
__device__ __half g_B[(size_t)NCOLS * DIM];
__device__ float  g_colmax[(size_t)BATCH * NCOLS];
__device__ float  g_scores[BATCH * BATCH];
__device__ float  g_red[BATCH];
__device__ int    g_cnt = 0;

__device__ __forceinline__ uint32_t s2u(const void* p) {
    return (uint32_t)__cvta_generic_to_shared(p);
}

// ============================================================================
// Kernel 1: L2-normalize + slice + fp16 convert. WARP-PER-ROW (no barriers).
//   8 rows per 256-thread block; lane reads 8 float4 (coalesced), shuffle
//   butterfly reduction, writes 8 uint2 (4 halves each).
// ============================================================================
__global__ __launch_bounds__(256) void norm_kernel(const float* __restrict__ im_in,
                                                   const float* __restrict__ s_in)
{
    int r = blockIdx.x * 8 + (threadIdx.x >> 5);   // global output row
    int lane = threadIdx.x & 31;
    if (r >= TROWS) return;

    int which = (r >= MROWS);
    int ob = which ? (r - MROWS) : r;
    const float* in = which ? s_in : im_in;
    int Lin  = which ? L_S : L_IM;
    int Lout = which ? LS  : LI;
    int b = ob / Lout;
    int i = ob % Lout;

    const float4* src = (const float4*)(in + ((size_t)b * Lin + i + 1) * DIM);
    float4 v[8];
    #pragma unroll
    for (int q = 0; q < 8; q++) v[q] = src[lane + 32 * q];

    float ss = 0.f;
    #pragma unroll
    for (int q = 0; q < 8; q++)
        ss += v[q].x*v[q].x + v[q].y*v[q].y + v[q].z*v[q].z + v[q].w*v[q].w;
    #pragma unroll
    for (int o = 16; o > 0; o >>= 1) ss += __shfl_xor_sync(0xffffffffu, ss, o);

    float inv = 1.0f / fmaxf(sqrtf(ss), 1e-12f);

    __half* dst = (which ? g_B : g_A) + (size_t)ob * DIM;
    #pragma unroll
    for (int q = 0; q < 8; q++) {
        __half2 h01 = __floats2half2_rn(v[q].x * inv, v[q].y * inv);
        __half2 h23 = __floats2half2_rn(v[q].z * inv, v[q].w * inv);
        uint2 w;
        w.x = *(uint32_t*)&h01;
        w.y = *(uint32_t*)&h23;
        *(uint2*)(dst + 4 * (lane + 32 * q)) = w;
    }
}

// ============================================================================
// Kernel 2: fp16 mma.sync GEMM with FUSED masked max-over-regions epilogue.
//   (byte-identical to R11 best: 144x128x64, 192 thr, occ 2, 3-stage pipe)
// ============================================================================
#define BM 144
#define BN 128
#define BKH 64
#define STAGES 3
#define ROWB 128
#define STAGE_BYTES ((BM + BN) * ROWB)   // 34816
#define KTILES (DIM / BKH)               // 16
#define NTH 192
#define ESTR 132
#define SMEM_SZ (STAGES * STAGE_BYTES)   // 104448

__device__ __forceinline__ void cp16(uint32_t dst, const void* src) {
    asm volatile("cp.async.cg.shared.global [%0], [%1], 16;" :: "r"(dst), "l"(src));
}
__device__ __forceinline__ uint32_t swz(int row, int seg) {
    return (uint32_t)(row * ROWB + ((seg ^ (row & 7)) << 4));
}
#define LDSM4(r, addr) \
    asm volatile("ldmatrix.sync.aligned.m8n8.x4.shared.b16 {%0,%1,%2,%3}, [%4];" \
        : "=r"((r)[0]), "=r"((r)[1]), "=r"((r)[2]), "=r"((r)[3]) : "r"(addr))
#define HMMA(acc, a0, a1, a2, a3, b0, b1) \
    asm volatile("mma.sync.aligned.m16n8k16.row.col.f32.f16.f16.f32 " \
        "{%0,%1,%2,%3}, {%4,%5,%6,%7}, {%8,%9}, {%0,%1,%2,%3};" \
        : "+f"((acc)[0]), "+f"((acc)[1]), "+f"((acc)[2]), "+f"((acc)[3]) \
        : "r"(a0), "r"(a1), "r"(a2), "r"(a3), "r"(b0), "r"(b1))

__device__ __forceinline__ void load_stage(char* dsm, int slot, int m0, int n0, int kc, int t)
{
    char* As = dsm + slot * STAGE_BYTES;
    char* Bs = As + BM * ROWB;
    const __half* Agp = g_A + (size_t)m0 * DIM + kc * BKH;
    const __half* Bgp = g_B + (size_t)n0 * DIM + kc * BKH;
    #pragma unroll
    for (int i = 0; i < 6; i++) {
        int idx = t + i * NTH;
        int row = idx >> 3, seg = idx & 7;
        cp16(s2u(As + swz(row, seg)), Agp + (size_t)row * DIM + seg * 8);
    }
    #pragma unroll
    for (int i = 0; i < 6; i++) {
        int idx = t + i * NTH;
        if (idx < 1024) {
            int row = idx >> 3, seg = idx & 7;
            cp16(s2u(Bs + swz(row, seg)), Bgp + (size_t)row * DIM + seg * 8);
        }
    }
}

__global__ __launch_bounds__(NTH, 2) void gemm_kernel(const int* __restrict__ im_len)
{
    extern __shared__ __align__(128) char dsm[];
    const int t   = threadIdx.x;
    const int wid = t >> 5, lid = t & 31;
    const int warp_m = (wid % 3) * 48;
    const int warp_n = (wid / 3) * 64;
    const int m0 = blockIdx.y * BM;
    const int n0 = blockIdx.x * BN;

    float acc[3][8][4];
    #pragma unroll
    for (int mf = 0; mf < 3; mf++)
        #pragma unroll
        for (int nf = 0; nf < 8; nf++)
            #pragma unroll
            for (int q = 0; q < 4; q++) acc[mf][nf][q] = 0.f;

    #pragma unroll
    for (int s = 0; s < STAGES - 1; s++) {
        load_stage(dsm, s, m0, n0, s, t);
        asm volatile("cp.async.commit_group;");
    }

    int rowA[3], rswA[3];
    #pragma unroll
    for (int mf = 0; mf < 3; mf++) {
        rowA[mf] = warp_m + mf * 16 + (lid & 15);
        rswA[mf] = rowA[mf] & 7;
    }
    const int a_seg0 = (lid >> 4);
    const int b_row_base = warp_n + ((lid >> 4) & 1) * 8 + (lid & 7);
    const int b_seg0 = (lid >> 3) & 1;

    int slot = 0, lslot = STAGES - 1;
    for (int j = 0; j < KTILES; j++) {
        if (j < KTILES - 1) asm volatile("cp.async.wait_group 1;");
        else                asm volatile("cp.async.wait_group 0;");
        __syncthreads();

        int jl = j + STAGES - 1;
        if (jl < KTILES) {
            load_stage(dsm, lslot, m0, n0, jl, t);
            asm volatile("cp.async.commit_group;");
        }

        const uint32_t AsU = s2u(dsm) + slot * STAGE_BYTES;
        const uint32_t BsU = AsU + BM * ROWB;

        #pragma unroll
        for (int ks = 0; ks < 4; ks++) {
            uint32_t a[3][4];
            #pragma unroll
            for (int mf = 0; mf < 3; mf++)
                LDSM4(a[mf], AsU + rowA[mf] * ROWB
                             + (((a_seg0 + 2 * ks) ^ rswA[mf]) << 4));
            uint32_t bf[4][4];
            #pragma unroll
            for (int np = 0; np < 4; np++) {
                int row = b_row_base + np * 16;
                LDSM4(bf[np], BsU + row * ROWB
                              + (((b_seg0 + 2 * ks) ^ (row & 7)) << 4));
            }
            #pragma unroll
            for (int nf = 0; nf < 8; nf++) {
                uint32_t b0 = bf[nf >> 1][(nf & 1) * 2];
                uint32_t b1 = bf[nf >> 1][(nf & 1) * 2 + 1];
                #pragma unroll
                for (int mf = 0; mf < 3; mf++)
                    HMMA(acc[mf][nf], a[mf][0], a[mf][1], a[mf][2], a[mf][3], b0, b1);
            }
        }
        slot  = (slot  == STAGES - 1) ? 0 : slot + 1;
        lslot = (lslot == STAGES - 1) ? 0 : lslot + 1;
    }

    __syncthreads();
    float* etile = (float*)dsm;
    const int r0 = warp_m + (lid >> 2);
    const int c0 = warp_n + (lid & 3) * 2;
    #pragma unroll
    for (int mf = 0; mf < 3; mf++) {
        #pragma unroll
        for (int nf = 0; nf < 8; nf++) {
            int r = r0 + mf * 16;
            int c = c0 + nf * 8;
            etile[r * ESTR + c]           = acc[mf][nf][0];
            etile[r * ESTR + c + 1]       = acc[mf][nf][1];
            etile[(r + 8) * ESTR + c]     = acc[mf][nf][2];
            etile[(r + 8) * ESTR + c + 1] = acc[mf][nf][3];
        }
    }
    __syncthreads();

    const int bimg0 = blockIdx.y * 4;
    for (int idx = t; idx < 512; idx += NTH) {
        int img = idx >> 7, col = idx & 127;
        int iml = im_len[bimg0 + img] - 1;
        const float* colp = etile + img * 36 * ESTR + col;
        float m = -1e30f;
        for (int r = 0; r < iml; r++) m = fmaxf(m, colp[r * ESTR]);
        if (iml < LI) m = fmaxf(m, 0.f);
        g_colmax[(size_t)(bimg0 + img) * NCOLS + n0 + col] = m;
    }
}

// ============================================================================
// Kernel 3: scores[b][c] = sum_{j < sl} colmax[b][c*30+j].
// ============================================================================
__global__ __launch_bounds__(256) void score_kernel(const int* __restrict__ s_len)
{
    __shared__ float row[NCOLS];
    const int b = blockIdx.x, t = threadIdx.x;
    const float4* src = (const float4*)(g_colmax + (size_t)b * NCOLS);
    #pragma unroll
    for (int i = 0; i < 8; i++) {
        int idx = t + i * 256;
        if (idx < NCOLS / 4)
            *(float4*)(row + 4 * idx) = src[idx];
    }
    __syncthreads();

    int sl = s_len[t] - 3;
    if (sl > LS) sl = LS;
    if (sl < 0)  sl = 0;
    const float* p = row + t * LS;
    float sum = 0.f;
    for (int j = 0; j < sl; j++) sum += p[j];
    g_scores[b * BATCH + t] = sum;
}

// ============================================================================
// Kernel 4: fused contrastive loss (last block reduces; counter self-resets)
// ============================================================================
__global__ void loss_kernel(float* __restrict__ out)
{
    int b = blockIdx.x, t = threadIdx.x;
    __shared__ float sd;
    __shared__ float w1[8], w2[8];
    if (t == 0) sd = g_scores[b * BATCH + b];
    __syncthreads();
    float d = sd;
    float v1 = 0.f, v2 = 0.f;
    if (t != b) {
        v1 = fmaxf(0.f, MARGIN + g_scores[b * BATCH + t] - d);
        v2 = fmaxf(0.f, MARGIN + g_scores[t * BATCH + b] - d);
    }
    #pragma unroll
    for (int o = 16; o > 0; o >>= 1) {
        v1 = fmaxf(v1, __shfl_down_sync(0xffffffffu, v1, o));
        v2 = fmaxf(v2, __shfl_down_sync(0xffffffffu, v2, o));
    }
    if ((t & 31) == 0) { w1[t >> 5] = v1; w2[t >> 5] = v2; }
    __syncthreads();

    __shared__ int is_last;
    if (t == 0) {
        float m1 = w1[0], m2 = w2[0];
        #pragma unroll
        for (int q = 1; q < 8; q++) { m1 = fmaxf(m1, w1[q]); m2 = fmaxf(m2, w2[q]); }
        g_red[b] = m1 + m2;
        __threadfence();
        is_last = (atomicAdd(&g_cnt, 1) == BATCH - 1);
    }
    __syncthreads();
    if (is_last) {
        __shared__ float sm[BATCH];
        sm[t] = g_red[t];
        __syncthreads();
        #pragma unroll
        for (int o = 128; o > 0; o >>= 1) {
            if (t < o) sm[t] += sm[t + o];
            __syncthreads();
        }
        if (t == 0) { out[0] = sm[0]; g_cnt = 0; }
    }
}

// ============================================================================
extern "C" void kernel_launch(void* const* d_in, const int* in_sizes, int n_in,
                              void* d_out, int out_size)
{
    const float* im_set = (const float*)d_in[0];
    const float* s_seq  = (const float*)d_in[1];
    const int*   im_len = (const int*)d_in[2];
    const int*   s_len  = (const int*)d_in[3];
    float* out = (float*)d_out;

    cudaFuncSetAttribute(gemm_kernel, cudaFuncAttributeMaxDynamicSharedMemorySize,
                         SMEM_SZ);

    norm_kernel<<<(TROWS + 7) / 8, 256>>>(im_set, s_seq);

    dim3 grid(NCOLS / BN, MROWS / BM);   // (60, 64)
    gemm_kernel<<<grid, NTH, SMEM_SZ>>>(im_len);

    score_kernel<<<BATCH, 256>>>(s_len);

    loss_kernel<<<BATCH, 256>>>(out);
}

// round 14
// speedup vs baseline: 1.0366x; 1.0028x over previous
#include <cuda_runtime.h>
#include <cuda_fp16.h>
#include <math.h>
#include <stdint.h>

// Problem constants
#define BATCH 256
#define DIM   1024
#define L_IM  37
#define L_S   33
#define LI    36
#define LS    30
#define MARGIN 0.2f

#define MROWS  (BATCH*LI)     // 9216
#define NCOLS  (BATCH*LS)     // 7680
#define TROWS  (MROWS + BATCH*LS)   // 16896 total output rows

// ---- device scratch (allocation-free rule) ----
__device__ __half g_A[(size_t)MROWS * DIM];
__device__ __half g_B[(size_t)NCOLS * DIM];
__device__ float  g_colmax[(size_t)BATCH * NCOLS];
__device__ float  g_red[BATCH];            // per-row cost_s max
__device__ float  g_diag[BATCH];           // scores diagonal
__device__ unsigned g_cmax[BATCH];         // encoded col-max of scores (zero-init = -inf)
__device__ int    g_cnt = 0;

__device__ __forceinline__ uint32_t s2u(const void* p) {
    return (uint32_t)__cvta_generic_to_shared(p);
}
// monotonic float<->uint encoding (order-preserving for atomicMax)
__device__ __forceinline__ unsigned fenc(float f) {
    unsigned b = __float_as_uint(f);
    return (b & 0x80000000u) ? ~b : (b | 0x80000000u);
}
__device__ __forceinline__ float fdec(unsigned k) {
    return __uint_as_float((k & 0x80000000u) ? (k & 0x7fffffffu) : ~k);
}

// ============================================================================
// Kernel 1: L2-normalize + slice + fp16 convert. WARP-PER-ROW (no barriers).
// ============================================================================
__global__ __launch_bounds__(256) void norm_kernel(const float* __restrict__ im_in,
                                                   const float* __restrict__ s_in)
{
    int r = blockIdx.x * 8 + (threadIdx.x >> 5);
    int lane = threadIdx.x & 31;
    if (r >= TROWS) return;

    int which = (r >= MROWS);
    int ob = which ? (r - MROWS) : r;
    const float* in = which ? s_in : im_in;
    int Lin  = which ? L_S : L_IM;
    int Lout = which ? LS  : LI;
    int b = ob / Lout;
    int i = ob % Lout;

    const float4* src = (const float4*)(in + ((size_t)b * Lin + i + 1) * DIM);
    float4 v[8];
    #pragma unroll
    for (int q = 0; q < 8; q++) v[q] = src[lane + 32 * q];

    float ss = 0.f;
    #pragma unroll
    for (int q = 0; q < 8; q++)
        ss += v[q].x*v[q].x + v[q].y*v[q].y + v[q].z*v[q].z + v[q].w*v[q].w;
    #pragma unroll
    for (int o = 16; o > 0; o >>= 1) ss += __shfl_xor_sync(0xffffffffu, ss, o);

    float inv = 1.0f / fmaxf(sqrtf(ss), 1e-12f);

    __half* dst = (which ? g_B : g_A) + (size_t)ob * DIM;
    #pragma unroll
    for (int q = 0; q < 8; q++) {
        __half2 h01 = __floats2half2_rn(v[q].x * inv, v[q].y * inv);
        __half2 h23 = __floats2half2_rn(v[q].z * inv, v[q].w * inv);
        uint2 w;
        w.x = *(uint32_t*)&h01;
        w.y = *(uint32_t*)&h23;
        *(uint2*)(dst + 4 * (lane + 32 * q)) = w;
    }
}

// ============================================================================
// Kernel 2: fp16 mma.sync GEMM with FUSED masked max-over-regions epilogue.
//   (byte-identical to R11/R13 best: 144x128x64, 192 thr, occ 2, 3-stage pipe)
// ============================================================================
#define BM 144
#define BN 128
#define BKH 64
#define STAGES 3
#define ROWB 128
#define STAGE_BYTES ((BM + BN) * ROWB)   // 34816
#define KTILES (DIM / BKH)               // 16
#define NTH 192
#define ESTR 132
#define SMEM_SZ (STAGES * STAGE_BYTES)   // 104448

__device__ __forceinline__ void cp16(uint32_t dst, const void* src) {
    asm volatile("cp.async.cg.shared.global [%0], [%1], 16;" :: "r"(dst), "l"(src));
}
__device__ __forceinline__ uint32_t swz(int row, int seg) {
    return (uint32_t)(row * ROWB + ((seg ^ (row & 7)) << 4));
}
#define LDSM4(r, addr) \
    asm volatile("ldmatrix.sync.aligned.m8n8.x4.shared.b16 {%0,%1,%2,%3}, [%4];" \
        : "=r"((r)[0]), "=r"((r)[1]), "=r"((r)[2]), "=r"((r)[3]) : "r"(addr))
#define HMMA(acc, a0, a1, a2, a3, b0, b1) \
    asm volatile("mma.sync.aligned.m16n8k16.row.col.f32.f16.f16.f32 " \
        "{%0,%1,%2,%3}, {%4,%5,%6,%7}, {%8,%9}, {%0,%1,%2,%3};" \
        : "+f"((acc)[0]), "+f"((acc)[1]), "+f"((acc)[2]), "+f"((acc)[3]) \
        : "r"(a0), "r"(a1), "r"(a2), "r"(a3), "r"(b0), "r"(b1))

__device__ __forceinline__ void load_stage(char* dsm, int slot, int m0, int n0, int kc, int t)
{
    char* As = dsm + slot * STAGE_BYTES;
    char* Bs = As + BM * ROWB;
    const __half* Agp = g_A + (size_t)m0 * DIM + kc * BKH;
    const __half* Bgp = g_B + (size_t)n0 * DIM + kc * BKH;
    #pragma unroll
    for (int i = 0; i < 6; i++) {
        int idx = t + i * NTH;
        int row = idx >> 3, seg = idx & 7;
        cp16(s2u(As + swz(row, seg)), Agp + (size_t)row * DIM + seg * 8);
    }
    #pragma unroll
    for (int i = 0; i < 6; i++) {
        int idx = t + i * NTH;
        if (idx < 1024) {
            int row = idx >> 3, seg = idx & 7;
            cp16(s2u(Bs + swz(row, seg)), Bgp + (size_t)row * DIM + seg * 8);
        }
    }
}

__global__ __launch_bounds__(NTH, 2) void gemm_kernel(const int* __restrict__ im_len)
{
    extern __shared__ __align__(128) char dsm[];
    const int t   = threadIdx.x;
    const int wid = t >> 5, lid = t & 31;
    const int warp_m = (wid % 3) * 48;
    const int warp_n = (wid / 3) * 64;
    const int m0 = blockIdx.y * BM;
    const int n0 = blockIdx.x * BN;

    float acc[3][8][4];
    #pragma unroll
    for (int mf = 0; mf < 3; mf++)
        #pragma unroll
        for (int nf = 0; nf < 8; nf++)
            #pragma unroll
            for (int q = 0; q < 4; q++) acc[mf][nf][q] = 0.f;

    #pragma unroll
    for (int s = 0; s < STAGES - 1; s++) {
        load_stage(dsm, s, m0, n0, s, t);
        asm volatile("cp.async.commit_group;");
    }

    int rowA[3], rswA[3];
    #pragma unroll
    for (int mf = 0; mf < 3; mf++) {
        rowA[mf] = warp_m + mf * 16 + (lid & 15);
        rswA[mf] = rowA[mf] & 7;
    }
    const int a_seg0 = (lid >> 4);
    const int b_row_base = warp_n + ((lid >> 4) & 1) * 8 + (lid & 7);
    const int b_seg0 = (lid >> 3) & 1;

    int slot = 0, lslot = STAGES - 1;
    for (int j = 0; j < KTILES; j++) {
        if (j < KTILES - 1) asm volatile("cp.async.wait_group 1;");
        else                asm volatile("cp.async.wait_group 0;");
        __syncthreads();

        int jl = j + STAGES - 1;
        if (jl < KTILES) {
            load_stage(dsm, lslot, m0, n0, jl, t);
            asm volatile("cp.async.commit_group;");
        }

        const uint32_t AsU = s2u(dsm) + slot * STAGE_BYTES;
        const uint32_t BsU = AsU + BM * ROWB;

        #pragma unroll
        for (int ks = 0; ks < 4; ks++) {
            uint32_t a[3][4];
            #pragma unroll
            for (int mf = 0; mf < 3; mf++)
                LDSM4(a[mf], AsU + rowA[mf] * ROWB
                             + (((a_seg0 + 2 * ks) ^ rswA[mf]) << 4));
            uint32_t bf[4][4];
            #pragma unroll
            for (int np = 0; np < 4; np++) {
                int row = b_row_base + np * 16;
                LDSM4(bf[np], BsU + row * ROWB
                              + (((b_seg0 + 2 * ks) ^ (row & 7)) << 4));
            }
            #pragma unroll
            for (int nf = 0; nf < 8; nf++) {
                uint32_t b0 = bf[nf >> 1][(nf & 1) * 2];
                uint32_t b1 = bf[nf >> 1][(nf & 1) * 2 + 1];
                #pragma unroll
                for (int mf = 0; mf < 3; mf++)
                    HMMA(acc[mf][nf], a[mf][0], a[mf][1], a[mf][2], a[mf][3], b0, b1);
            }
        }
        slot  = (slot  == STAGES - 1) ? 0 : slot + 1;
        lslot = (lslot == STAGES - 1) ? 0 : lslot + 1;
    }

    __syncthreads();
    float* etile = (float*)dsm;
    const int r0 = warp_m + (lid >> 2);
    const int c0 = warp_n + (lid & 3) * 2;
    #pragma unroll
    for (int mf = 0; mf < 3; mf++) {
        #pragma unroll
        for (int nf = 0; nf < 8; nf++) {
            int r = r0 + mf * 16;
            int c = c0 + nf * 8;
            etile[r * ESTR + c]           = acc[mf][nf][0];
            etile[r * ESTR + c + 1]       = acc[mf][nf][1];
            etile[(r + 8) * ESTR + c]     = acc[mf][nf][2];
            etile[(r + 8) * ESTR + c + 1] = acc[mf][nf][3];
        }
    }
    __syncthreads();

    const int bimg0 = blockIdx.y * 4;
    for (int idx = t; idx < 512; idx += NTH) {
        int img = idx >> 7, col = idx & 127;
        int iml = im_len[bimg0 + img] - 1;
        const float* colp = etile + img * 36 * ESTR + col;
        float m = -1e30f;
        for (int r = 0; r < iml; r++) m = fmaxf(m, colp[r * ESTR]);
        if (iml < LI) m = fmaxf(m, 0.f);
        g_colmax[(size_t)(bimg0 + img) * NCOLS + n0 + col] = m;
    }
}

// ============================================================================
// Kernel 3 (score + FULL loss):
//   Block b: scores row b (smem) -> cost_s row-max locally (diag local),
//   atomicMax contribution to each column's scores-max (order-independent),
//   diag write. Last block (counter): O(1)/thread combine + reduce.
//   Self-resets g_cnt and g_cmax for graph replay determinism.
// ============================================================================
__global__ __launch_bounds__(256) void scoreloss_kernel(const int* __restrict__ s_len,
                                                        float* __restrict__ out)
{
    __shared__ float row[NCOLS];
    __shared__ float srow[BATCH];
    const int b = blockIdx.x, t = threadIdx.x;

    const float4* src = (const float4*)(g_colmax + (size_t)b * NCOLS);
    #pragma unroll
    for (int i = 0; i < 8; i++) {
        int idx = t + i * 256;
        if (idx < NCOLS / 4)
            *(float4*)(row + 4 * idx) = src[idx];
    }
    __syncthreads();

    int sl = s_len[t] - 3;
    if (sl > LS) sl = LS;
    if (sl < 0)  sl = 0;
    const float* p = row + t * LS;
    float sc = 0.f;
    for (int j = 0; j < sl; j++) sc += p[j];
    srow[t] = sc;
    __syncthreads();

    // cost_s row-max (diag local to this block)
    float d = srow[b];
    float v1 = (t != b) ? fmaxf(0.f, MARGIN + sc - d) : 0.f;
    #pragma unroll
    for (int o = 16; o > 0; o >>= 1)
        v1 = fmaxf(v1, __shfl_down_sync(0xffffffffu, v1, o));
    __shared__ float w1[8];
    if ((t & 31) == 0) w1[t >> 5] = v1;

    // column contributions (order-independent atomic max) + diag
    if (t != b) atomicMax(&g_cmax[t], fenc(sc));
    else        g_diag[b] = sc;
    __syncthreads();

    __shared__ int is_last;
    if (t == 0) {
        float m1 = w1[0];
        #pragma unroll
        for (int q = 1; q < 8; q++) m1 = fmaxf(m1, w1[q]);
        g_red[b] = m1;
        __threadfence();
        is_last = (atomicAdd(&g_cnt, 1) == BATCH - 1);
    }
    __syncthreads();

    if (is_last) {
        float cm = fmaxf(0.f, MARGIN + fdec(g_cmax[t]) - g_diag[t]);
        __shared__ float sm[BATCH];
        sm[t] = g_red[t] + cm;
        g_cmax[t] = 0u;                    // reset for next graph replay
        __syncthreads();
        #pragma unroll
        for (int o = 128; o > 0; o >>= 1) {
            if (t < o) sm[t] += sm[t + o];
            __syncthreads();
        }
        if (t == 0) { out[0] = sm[0]; g_cnt = 0; }
    }
}

// ============================================================================
extern "C" void kernel_launch(void* const* d_in, const int* in_sizes, int n_in,
                              void* d_out, int out_size)
{
    const float* im_set = (const float*)d_in[0];
    const float* s_seq  = (const float*)d_in[1];
    const int*   im_len = (const int*)d_in[2];
    const int*   s_len  = (const int*)d_in[3];
    float* out = (float*)d_out;

    cudaFuncSetAttribute(gemm_kernel, cudaFuncAttributeMaxDynamicSharedMemorySize,
                         SMEM_SZ);

    norm_kernel<<<(TROWS + 7) / 8, 256>>>(im_set, s_seq);

    dim3 grid(NCOLS / BN, MROWS / BM);   // (60, 64)
    gemm_kernel<<<grid, NTH, SMEM_SZ>>>(im_len);

    scoreloss_kernel<<<BATCH, 256>>>(s_len, out);
}

// round 15
// speedup vs baseline: 1.0673x; 1.0296x over previous
#include <cuda_runtime.h>
#include <cuda_fp16.h>
#include <math.h>
#include <stdint.h>

// Problem constants
#define BATCH 256
#define DIM   1024
#define L_IM  37
#define L_S   33
#define LI    36
#define LS    30
#define MARGIN 0.2f

#define MROWS  (BATCH*LI)     // 9216
#define NCOLS  (BATCH*LS)     // 7680
#define TROWS  (MROWS + BATCH*LS)

// ---- device scratch (allocation-free rule) ----
__device__ __half g_A[(size_t)MROWS * DIM];
__device__ __half g_B[(size_t)NCOLS * DIM];
__device__ unsigned g_colmax_u[(size_t)BATCH * NCOLS];  // encoded col-max (0 = sentinel < all)
__device__ float  g_red[BATCH];
__device__ float  g_diag[BATCH];
__device__ unsigned g_cmax[BATCH];
__device__ int    g_cnt = 0;

__device__ __forceinline__ uint32_t s2u(const void* p) {
    return (uint32_t)__cvta_generic_to_shared(p);
}
// monotonic float<->uint encoding (order-preserving for atomicMax)
__device__ __forceinline__ unsigned fenc(float f) {
    unsigned b = __float_as_uint(f);
    return (b & 0x80000000u) ? ~b : (b | 0x80000000u);
}
__device__ __forceinline__ float fdec(unsigned k) {
    return __uint_as_float((k & 0x80000000u) ? (k & 0x7fffffffu) : ~k);
}

// ============================================================================
// Kernel 1: L2-normalize + slice + fp16 convert. WARP-PER-ROW (no barriers).
// ============================================================================
__global__ __launch_bounds__(256) void norm_kernel(const float* __restrict__ im_in,
                                                   const float* __restrict__ s_in)
{
    int r = blockIdx.x * 8 + (threadIdx.x >> 5);
    int lane = threadIdx.x & 31;
    if (r >= TROWS) return;

    int which = (r >= MROWS);
    int ob = which ? (r - MROWS) : r;
    const float* in = which ? s_in : im_in;
    int Lin  = which ? L_S : L_IM;
    int Lout = which ? LS  : LI;
    int b = ob / Lout;
    int i = ob % Lout;

    const float4* src = (const float4*)(in + ((size_t)b * Lin + i + 1) * DIM);
    float4 v[8];
    #pragma unroll
    for (int q = 0; q < 8; q++) v[q] = src[lane + 32 * q];

    float ss = 0.f;
    #pragma unroll
    for (int q = 0; q < 8; q++)
        ss += v[q].x*v[q].x + v[q].y*v[q].y + v[q].z*v[q].z + v[q].w*v[q].w;
    #pragma unroll
    for (int o = 16; o > 0; o >>= 1) ss += __shfl_xor_sync(0xffffffffu, ss, o);

    float inv = 1.0f / fmaxf(sqrtf(ss), 1e-12f);

    __half* dst = (which ? g_B : g_A) + (size_t)ob * DIM;
    #pragma unroll
    for (int q = 0; q < 8; q++) {
        __half2 h01 = __floats2half2_rn(v[q].x * inv, v[q].y * inv);
        __half2 h23 = __floats2half2_rn(v[q].z * inv, v[q].w * inv);
        uint2 w;
        w.x = *(uint32_t*)&h01;
        w.y = *(uint32_t*)&h23;
        *(uint2*)(dst + 4 * (lane + 32 * q)) = w;
    }
}

// ============================================================================
// Kernel 2: fp16 mma.sync GEMM, 128x128x64 CTA, 256 threads (8 warps =
//   SMSP-BALANCED: 4 tensor warps per SMSP at occ 2), warp tile 64x32,
//   3-stage cp.async pipeline, SW128 swizzle.
//   Epilogue: masked per-image column max -> encoded atomicMax (cross-CTA).
// ============================================================================
#define BM 128
#define BN 128
#define BKH 64
#define STAGES 3
#define ROWB 128
#define STAGE_BYTES ((BM + BN) * ROWB)   // 32768
#define KTILES (DIM / BKH)               // 16
#define NTH 256
#define ESTR 132
#define SMEM_SZ (STAGES * STAGE_BYTES)   // 98304

__device__ __forceinline__ void cp16(uint32_t dst, const void* src) {
    asm volatile("cp.async.cg.shared.global [%0], [%1], 16;" :: "r"(dst), "l"(src));
}
__device__ __forceinline__ uint32_t swz(int row, int seg) {
    return (uint32_t)(row * ROWB + ((seg ^ (row & 7)) << 4));
}
#define LDSM4(r, addr) \
    asm volatile("ldmatrix.sync.aligned.m8n8.x4.shared.b16 {%0,%1,%2,%3}, [%4];" \
        : "=r"((r)[0]), "=r"((r)[1]), "=r"((r)[2]), "=r"((r)[3]) : "r"(addr))
#define HMMA(acc, a0, a1, a2, a3, b0, b1) \
    asm volatile("mma.sync.aligned.m16n8k16.row.col.f32.f16.f16.f32 " \
        "{%0,%1,%2,%3}, {%4,%5,%6,%7}, {%8,%9}, {%0,%1,%2,%3};" \
        : "+f"((acc)[0]), "+f"((acc)[1]), "+f"((acc)[2]), "+f"((acc)[3]) \
        : "r"(a0), "r"(a1), "r"(a2), "r"(a3), "r"(b0), "r"(b1))

__device__ __forceinline__ void load_stage(char* dsm, int slot, int m0, int n0, int kc, int t)
{
    char* As = dsm + slot * STAGE_BYTES;
    char* Bs = As + BM * ROWB;
    const __half* Agp = g_A + (size_t)m0 * DIM + kc * BKH;
    const __half* Bgp = g_B + (size_t)n0 * DIM + kc * BKH;
    #pragma unroll
    for (int i = 0; i < 4; i++) {                 // 1024 A-vectors
        int idx = t + i * NTH;
        int row = idx >> 3, seg = idx & 7;
        cp16(s2u(As + swz(row, seg)), Agp + (size_t)row * DIM + seg * 8);
    }
    #pragma unroll
    for (int i = 0; i < 4; i++) {                 // 1024 B-vectors
        int idx = t + i * NTH;
        int row = idx >> 3, seg = idx & 7;
        cp16(s2u(Bs + swz(row, seg)), Bgp + (size_t)row * DIM + seg * 8);
    }
}

__global__ __launch_bounds__(NTH, 2) void gemm_kernel(const int* __restrict__ im_len)
{
    extern __shared__ __align__(128) char dsm[];
    const int t   = threadIdx.x;
    const int wid = t >> 5, lid = t & 31;
    const int warp_m = (wid & 1) * 64;       // 2 m-groups of 64
    const int warp_n = (wid >> 1) * 32;      // 4 n-groups of 32
    const int m0 = blockIdx.y * BM;
    const int n0 = blockIdx.x * BN;

    float acc[4][4][4];
    #pragma unroll
    for (int mf = 0; mf < 4; mf++)
        #pragma unroll
        for (int nf = 0; nf < 4; nf++)
            #pragma unroll
            for (int q = 0; q < 4; q++) acc[mf][nf][q] = 0.f;

    #pragma unroll
    for (int s = 0; s < STAGES - 1; s++) {
        load_stage(dsm, s, m0, n0, s, t);
        asm volatile("cp.async.commit_group;");
    }

    int rowA[4], rswA[4];
    #pragma unroll
    for (int mf = 0; mf < 4; mf++) {
        rowA[mf] = warp_m + mf * 16 + (lid & 15);
        rswA[mf] = rowA[mf] & 7;
    }
    const int a_seg0 = (lid >> 4);
    const int b_row_base = warp_n + ((lid >> 4) & 1) * 8 + (lid & 7);
    const int b_seg0 = (lid >> 3) & 1;

    int slot = 0, lslot = STAGES - 1;
    for (int j = 0; j < KTILES; j++) {
        if (j < KTILES - 1) asm volatile("cp.async.wait_group 1;");
        else                asm volatile("cp.async.wait_group 0;");
        __syncthreads();

        int jl = j + STAGES - 1;
        if (jl < KTILES) {
            load_stage(dsm, lslot, m0, n0, jl, t);
            asm volatile("cp.async.commit_group;");
        }

        const uint32_t AsU = s2u(dsm) + slot * STAGE_BYTES;
        const uint32_t BsU = AsU + BM * ROWB;

        #pragma unroll
        for (int ks = 0; ks < 4; ks++) {
            uint32_t a[4][4];
            #pragma unroll
            for (int mf = 0; mf < 4; mf++)
                LDSM4(a[mf], AsU + rowA[mf] * ROWB
                             + (((a_seg0 + 2 * ks) ^ rswA[mf]) << 4));
            uint32_t bf[2][4];
            #pragma unroll
            for (int np = 0; np < 2; np++) {
                int row = b_row_base + np * 16;
                LDSM4(bf[np], BsU + row * ROWB
                              + (((b_seg0 + 2 * ks) ^ (row & 7)) << 4));
            }
            #pragma unroll
            for (int nf = 0; nf < 4; nf++) {
                uint32_t b0 = bf[nf >> 1][(nf & 1) * 2];
                uint32_t b1 = bf[nf >> 1][(nf & 1) * 2 + 1];
                #pragma unroll
                for (int mf = 0; mf < 4; mf++)
                    HMMA(acc[mf][nf], a[mf][0], a[mf][1], a[mf][2], a[mf][3], b0, b1);
            }
        }
        slot  = (slot  == STAGES - 1) ? 0 : slot + 1;
        lslot = (lslot == STAGES - 1) ? 0 : lslot + 1;
    }

    // ---- epilogue: accs -> smem fp32 tile [128][128] (stride ESTR) ----
    __syncthreads();
    float* etile = (float*)dsm;                   // 128*132*4 = 67584 B < SMEM_SZ
    const int r0 = warp_m + (lid >> 2);
    const int c0 = warp_n + (lid & 3) * 2;
    #pragma unroll
    for (int mf = 0; mf < 4; mf++) {
        #pragma unroll
        for (int nf = 0; nf < 4; nf++) {
            int r = r0 + mf * 16;
            int c = c0 + nf * 8;
            etile[r * ESTR + c]           = acc[mf][nf][0];
            etile[r * ESTR + c + 1]       = acc[mf][nf][1];
            etile[(r + 8) * ESTR + c]     = acc[mf][nf][2];
            etile[(r + 8) * ESTR + c + 1] = acc[mf][nf][3];
        }
    }
    __syncthreads();

    // masked partial column max for each image intersecting [m0, m0+128)
    const int i0 = m0 / LI;
    const int i1 = (m0 + BM - 1) / LI;            // <= i0 + 4
    for (int idx = t; idx < 5 * BN; idx += NTH) {
        int img = i0 + (idx >> 7);
        if (img > i1) continue;
        int col = idx & 127;
        int iml = im_len[img] - 1;                // valid rows of this image
        int rs = img * LI - m0;                   // local row of image start
        int re = rs + (iml < LI ? iml : LI);      // local end (valid rows only)
        if (rs < 0) rs = 0;
        if (re > BM) re = BM;
        if (rs >= re) continue;                   // no valid rows in this CTA
        const float* colp = etile + col;
        float m = -1e30f;
        for (int r = rs; r < re; r++) m = fmaxf(m, colp[r * ESTR]);
        atomicMax(&g_colmax_u[(size_t)img * NCOLS + n0 + col], fenc(m));
    }
}

// ============================================================================
// Kernel 3 (score + loss): block b decodes colmax row b (applying pad-zero
//   join), resets it for replay, computes scores row b, cost_s row-max,
//   atomicMax col contributions; last block combines. Self-resets all state.
// ============================================================================
__global__ __launch_bounds__(256) void scoreloss_kernel(const int* __restrict__ im_len,
                                                        const int* __restrict__ s_len,
                                                        float* __restrict__ out)
{
    __shared__ float row[NCOLS];
    __shared__ float srow[BATCH];
    const int b = blockIdx.x, t = threadIdx.x;

    float zjoin = (im_len[b] - 1 < LI) ? 0.f : -1e30f;   // reference zeros padded rows
    unsigned* src = g_colmax_u + (size_t)b * NCOLS;
    #pragma unroll
    for (int i = 0; i < 8; i++) {
        int idx0 = (t + i * 256) * 4;
        if (idx0 < NCOLS) {
            uint4 e = *(uint4*)(src + idx0);
            row[idx0 + 0] = fmaxf(fdec(e.x), zjoin);
            row[idx0 + 1] = fmaxf(fdec(e.y), zjoin);
            row[idx0 + 2] = fmaxf(fdec(e.z), zjoin);
            row[idx0 + 3] = fmaxf(fdec(e.w), zjoin);
            *(uint4*)(src + idx0) = make_uint4(0u, 0u, 0u, 0u);  // reset for replay
        }
    }
    __syncthreads();

    int sl = s_len[t] - 3;
    if (sl > LS) sl = LS;
    if (sl < 0)  sl = 0;
    const float* p = row + t * LS;
    float sc = 0.f;
    for (int j = 0; j < sl; j++) sc += p[j];
    srow[t] = sc;
    __syncthreads();

    float d = srow[b];
    float v1 = (t != b) ? fmaxf(0.f, MARGIN + sc - d) : 0.f;
    #pragma unroll
    for (int o = 16; o > 0; o >>= 1)
        v1 = fmaxf(v1, __shfl_down_sync(0xffffffffu, v1, o));
    __shared__ float w1[8];
    if ((t & 31) == 0) w1[t >> 5] = v1;

    if (t != b) atomicMax(&g_cmax[t], fenc(sc));
    else        g_diag[b] = sc;
    __syncthreads();

    __shared__ int is_last;
    if (t == 0) {
        float m1 = w1[0];
        #pragma unroll
        for (int q = 1; q < 8; q++) m1 = fmaxf(m1, w1[q]);
        g_red[b] = m1;
        __threadfence();
        is_last = (atomicAdd(&g_cnt, 1) == BATCH - 1);
    }
    __syncthreads();

    if (is_last) {
        float cm = fmaxf(0.f, MARGIN + fdec(g_cmax[t]) - g_diag[t]);
        __shared__ float sm[BATCH];
        sm[t] = g_red[t] + cm;
        g_cmax[t] = 0u;
        __syncthreads();
        #pragma unroll
        for (int o = 128; o > 0; o >>= 1) {
            if (t < o) sm[t] += sm[t + o];
            __syncthreads();
        }
        if (t == 0) { out[0] = sm[0]; g_cnt = 0; }
    }
}

// ============================================================================
extern "C" void kernel_launch(void* const* d_in, const int* in_sizes, int n_in,
                              void* d_out, int out_size)
{
    const float* im_set = (const float*)d_in[0];
    const float* s_seq  = (const float*)d_in[1];
    const int*   im_len = (const int*)d_in[2];
    const int*   s_len  = (const int*)d_in[3];
    float* out = (float*)d_out;

    cudaFuncSetAttribute(gemm_kernel, cudaFuncAttributeMaxDynamicSharedMemorySize,
                         SMEM_SZ);

    norm_kernel<<<(TROWS + 7) / 8, 256>>>(im_set, s_seq);

    dim3 grid(NCOLS / BN, MROWS / BM);   // (60, 72)
    gemm_kernel<<<grid, NTH, SMEM_SZ>>>(im_len);

    scoreloss_kernel<<<BATCH, 256>>>(im_len, s_len, out);
}

// round 16
// speedup vs baseline: 1.1319x; 1.0606x over previous
#include <cuda_runtime.h>
#include <cuda_fp16.h>
#include <math.h>
#include <stdint.h>

// Problem constants
#define BATCH 256
#define DIM   1024
#define L_IM  37
#define L_S   33
#define LI    36
#define LS    30
#define MARGIN 0.2f

#define MROWS  (BATCH*LI)     // 9216
#define NCOLS  (BATCH*LS)     // 7680
#define TROWS  (MROWS + BATCH*LS)

// ---- device scratch (allocation-free rule) ----
__device__ __half g_A[(size_t)MROWS * DIM];
__device__ __half g_B[(size_t)NCOLS * DIM];
__device__ unsigned g_colmax_u[(size_t)BATCH * NCOLS];  // encoded col-max (0 = sentinel)
__device__ float  g_red[BATCH];
__device__ float  g_diag[BATCH];
__device__ unsigned g_cmax[BATCH];
__device__ int    g_cnt = 0;

__device__ __forceinline__ uint32_t s2u(const void* p) {
    return (uint32_t)__cvta_generic_to_shared(p);
}
// monotonic float<->uint encoding (order-preserving for atomicMax)
__device__ __forceinline__ unsigned fenc(float f) {
    unsigned b = __float_as_uint(f);
    return (b & 0x80000000u) ? ~b : (b | 0x80000000u);
}
__device__ __forceinline__ float fdec(unsigned k) {
    return __uint_as_float((k & 0x80000000u) ? (k & 0x7fffffffu) : ~k);
}

// ============================================================================
// Kernel 1: L2-normalize + slice + fp16 convert. WARP-PER-ROW (no barriers).
// ============================================================================
__global__ __launch_bounds__(256) void norm_kernel(const float* __restrict__ im_in,
                                                   const float* __restrict__ s_in)
{
    int r = blockIdx.x * 8 + (threadIdx.x >> 5);
    int lane = threadIdx.x & 31;
    if (r >= TROWS) return;

    int which = (r >= MROWS);
    int ob = which ? (r - MROWS) : r;
    const float* in = which ? s_in : im_in;
    int Lin  = which ? L_S : L_IM;
    int Lout = which ? LS  : LI;
    int b = ob / Lout;
    int i = ob % Lout;

    const float4* src = (const float4*)(in + ((size_t)b * Lin + i + 1) * DIM);
    float4 v[8];
    #pragma unroll
    for (int q = 0; q < 8; q++) v[q] = src[lane + 32 * q];

    float ss = 0.f;
    #pragma unroll
    for (int q = 0; q < 8; q++)
        ss += v[q].x*v[q].x + v[q].y*v[q].y + v[q].z*v[q].z + v[q].w*v[q].w;
    #pragma unroll
    for (int o = 16; o > 0; o >>= 1) ss += __shfl_xor_sync(0xffffffffu, ss, o);

    float inv = 1.0f / fmaxf(sqrtf(ss), 1e-12f);

    __half* dst = (which ? g_B : g_A) + (size_t)ob * DIM;
    #pragma unroll
    for (int q = 0; q < 8; q++) {
        __half2 h01 = __floats2half2_rn(v[q].x * inv, v[q].y * inv);
        __half2 h23 = __floats2half2_rn(v[q].z * inv, v[q].w * inv);
        uint2 w;
        w.x = *(uint32_t*)&h01;
        w.y = *(uint32_t*)&h23;
        *(uint2*)(dst + 4 * (lane + 32 * q)) = w;
    }
}

// ============================================================================
// Kernel 2: fp16 mma.sync GEMM, 128x128x64 CTA, 128 threads (4 warps of
//   64x64 in 2m x 2n grid -> A/B smem duplication x2 each: crossbar 75%
//   of tensor floor instead of 100%), occ 2 (8 warps/SM, SMSP-balanced),
//   3-stage cp.async pipeline, SW128 swizzle.
//   Epilogue: masked per-image column max -> encoded atomicMax (cross-CTA).
// ============================================================================
#define BM 128
#define BN 128
#define BKH 64
#define STAGES 3
#define ROWB 128
#define STAGE_BYTES ((BM + BN) * ROWB)   // 32768
#define KTILES (DIM / BKH)               // 16
#define NTH 128
#define ESTR 132
#define SMEM_SZ (STAGES * STAGE_BYTES)   // 98304

__device__ __forceinline__ void cp16(uint32_t dst, const void* src) {
    asm volatile("cp.async.cg.shared.global [%0], [%1], 16;" :: "r"(dst), "l"(src));
}
__device__ __forceinline__ uint32_t swz(int row, int seg) {
    return (uint32_t)(row * ROWB + ((seg ^ (row & 7)) << 4));
}
#define LDSM4(r, addr) \
    asm volatile("ldmatrix.sync.aligned.m8n8.x4.shared.b16 {%0,%1,%2,%3}, [%4];" \
        : "=r"((r)[0]), "=r"((r)[1]), "=r"((r)[2]), "=r"((r)[3]) : "r"(addr))
#define HMMA(acc, a0, a1, a2, a3, b0, b1) \
    asm volatile("mma.sync.aligned.m16n8k16.row.col.f32.f16.f16.f32 " \
        "{%0,%1,%2,%3}, {%4,%5,%6,%7}, {%8,%9}, {%0,%1,%2,%3};" \
        : "+f"((acc)[0]), "+f"((acc)[1]), "+f"((acc)[2]), "+f"((acc)[3]) \
        : "r"(a0), "r"(a1), "r"(a2), "r"(a3), "r"(b0), "r"(b1))

__device__ __forceinline__ void load_stage(char* dsm, int slot, int m0, int n0, int kc, int t)
{
    char* As = dsm + slot * STAGE_BYTES;
    char* Bs = As + BM * ROWB;
    const __half* Agp = g_A + (size_t)m0 * DIM + kc * BKH;
    const __half* Bgp = g_B + (size_t)n0 * DIM + kc * BKH;
    #pragma unroll
    for (int i = 0; i < 8; i++) {                 // 1024 A-vectors
        int idx = t + i * NTH;
        int row = idx >> 3, seg = idx & 7;
        cp16(s2u(As + swz(row, seg)), Agp + (size_t)row * DIM + seg * 8);
    }
    #pragma unroll
    for (int i = 0; i < 8; i++) {                 // 1024 B-vectors
        int idx = t + i * NTH;
        int row = idx >> 3, seg = idx & 7;
        cp16(s2u(Bs + swz(row, seg)), Bgp + (size_t)row * DIM + seg * 8);
    }
}

__global__ __launch_bounds__(NTH, 2) void gemm_kernel(const int* __restrict__ im_len)
{
    extern __shared__ __align__(128) char dsm[];
    const int t   = threadIdx.x;
    const int wid = t >> 5, lid = t & 31;
    const int warp_m = (wid & 1) * 64;       // 2 m-groups of 64
    const int warp_n = (wid >> 1) * 64;      // 2 n-groups of 64
    const int m0 = blockIdx.y * BM;
    const int n0 = blockIdx.x * BN;

    float acc[4][8][4];
    #pragma unroll
    for (int mf = 0; mf < 4; mf++)
        #pragma unroll
        for (int nf = 0; nf < 8; nf++)
            #pragma unroll
            for (int q = 0; q < 4; q++) acc[mf][nf][q] = 0.f;

    #pragma unroll
    for (int s = 0; s < STAGES - 1; s++) {
        load_stage(dsm, s, m0, n0, s, t);
        asm volatile("cp.async.commit_group;");
    }

    int rowA[4], rswA[4];
    #pragma unroll
    for (int mf = 0; mf < 4; mf++) {
        rowA[mf] = warp_m + mf * 16 + (lid & 15);
        rswA[mf] = rowA[mf] & 7;
    }
    const int a_seg0 = (lid >> 4);
    const int b_row_base = warp_n + ((lid >> 4) & 1) * 8 + (lid & 7);
    const int b_seg0 = (lid >> 3) & 1;

    int slot = 0, lslot = STAGES - 1;
    for (int j = 0; j < KTILES; j++) {
        if (j < KTILES - 1) asm volatile("cp.async.wait_group 1;");
        else                asm volatile("cp.async.wait_group 0;");
        __syncthreads();

        int jl = j + STAGES - 1;
        if (jl < KTILES) {
            load_stage(dsm, lslot, m0, n0, jl, t);
            asm volatile("cp.async.commit_group;");
        }

        const uint32_t AsU = s2u(dsm) + slot * STAGE_BYTES;
        const uint32_t BsU = AsU + BM * ROWB;

        #pragma unroll
        for (int ks = 0; ks < 4; ks++) {
            uint32_t a[4][4];
            #pragma unroll
            for (int mf = 0; mf < 4; mf++)
                LDSM4(a[mf], AsU + rowA[mf] * ROWB
                             + (((a_seg0 + 2 * ks) ^ rswA[mf]) << 4));
            uint32_t bf[4][4];
            #pragma unroll
            for (int np = 0; np < 4; np++) {
                int row = b_row_base + np * 16;
                LDSM4(bf[np], BsU + row * ROWB
                              + (((b_seg0 + 2 * ks) ^ (row & 7)) << 4));
            }
            #pragma unroll
            for (int nf = 0; nf < 8; nf++) {
                uint32_t b0 = bf[nf >> 1][(nf & 1) * 2];
                uint32_t b1 = bf[nf >> 1][(nf & 1) * 2 + 1];
                #pragma unroll
                for (int mf = 0; mf < 4; mf++)
                    HMMA(acc[mf][nf], a[mf][0], a[mf][1], a[mf][2], a[mf][3], b0, b1);
            }
        }
        slot  = (slot  == STAGES - 1) ? 0 : slot + 1;
        lslot = (lslot == STAGES - 1) ? 0 : lslot + 1;
    }

    // ---- epilogue: accs -> smem fp32 tile [128][128] (stride ESTR) ----
    __syncthreads();
    float* etile = (float*)dsm;                   // 128*132*4 = 67584 B < SMEM_SZ
    const int r0 = warp_m + (lid >> 2);
    const int c0 = warp_n + (lid & 3) * 2;
    #pragma unroll
    for (int mf = 0; mf < 4; mf++) {
        #pragma unroll
        for (int nf = 0; nf < 8; nf++) {
            int r = r0 + mf * 16;
            int c = c0 + nf * 8;
            etile[r * ESTR + c]           = acc[mf][nf][0];
            etile[r * ESTR + c + 1]       = acc[mf][nf][1];
            etile[(r + 8) * ESTR + c]     = acc[mf][nf][2];
            etile[(r + 8) * ESTR + c + 1] = acc[mf][nf][3];
        }
    }
    __syncthreads();

    // masked partial column max for each image intersecting [m0, m0+128)
    const int i0 = m0 / LI;
    const int i1 = (m0 + BM - 1) / LI;            // <= i0 + 4
    for (int idx = t; idx < 5 * BN; idx += NTH) {
        int img = i0 + (idx >> 7);
        if (img > i1) continue;
        int col = idx & 127;
        int iml = im_len[img] - 1;
        int rs = img * LI - m0;
        int re = rs + (iml < LI ? iml : LI);
        if (rs < 0) rs = 0;
        if (re > BM) re = BM;
        if (rs >= re) continue;
        const float* colp = etile + col;
        float m = -1e30f;
        for (int r = rs; r < re; r++) m = fmaxf(m, colp[r * ESTR]);
        atomicMax(&g_colmax_u[(size_t)img * NCOLS + n0 + col], fenc(m));
    }
}

// ============================================================================
// Kernel 3 (score + loss): block b decodes colmax row b (pad-zero join),
//   resets it, computes scores row b, cost_s row-max, atomicMax col
//   contributions; last block combines. Self-resets all state.
// ============================================================================
__global__ __launch_bounds__(256) void scoreloss_kernel(const int* __restrict__ im_len,
                                                        const int* __restrict__ s_len,
                                                        float* __restrict__ out)
{
    __shared__ float row[NCOLS];
    __shared__ float srow[BATCH];
    const int b = blockIdx.x, t = threadIdx.x;

    float zjoin = (im_len[b] - 1 < LI) ? 0.f : -1e30f;
    unsigned* src = g_colmax_u + (size_t)b * NCOLS;
    #pragma unroll
    for (int i = 0; i < 8; i++) {
        int idx0 = (t + i * 256) * 4;
        if (idx0 < NCOLS) {
            uint4 e = *(uint4*)(src + idx0);
            row[idx0 + 0] = fmaxf(fdec(e.x), zjoin);
            row[idx0 + 1] = fmaxf(fdec(e.y), zjoin);
            row[idx0 + 2] = fmaxf(fdec(e.z), zjoin);
            row[idx0 + 3] = fmaxf(fdec(e.w), zjoin);
            *(uint4*)(src + idx0) = make_uint4(0u, 0u, 0u, 0u);
        }
    }
    __syncthreads();

    int sl = s_len[t] - 3;
    if (sl > LS) sl = LS;
    if (sl < 0)  sl = 0;
    const float* p = row + t * LS;
    float sc = 0.f;
    for (int j = 0; j < sl; j++) sc += p[j];
    srow[t] = sc;
    __syncthreads();

    float d = srow[b];
    float v1 = (t != b) ? fmaxf(0.f, MARGIN + sc - d) : 0.f;
    #pragma unroll
    for (int o = 16; o > 0; o >>= 1)
        v1 = fmaxf(v1, __shfl_down_sync(0xffffffffu, v1, o));
    __shared__ float w1[8];
    if ((t & 31) == 0) w1[t >> 5] = v1;

    if (t != b) atomicMax(&g_cmax[t], fenc(sc));
    else        g_diag[b] = sc;
    __syncthreads();

    __shared__ int is_last;
    if (t == 0) {
        float m1 = w1[0];
        #pragma unroll
        for (int q = 1; q < 8; q++) m1 = fmaxf(m1, w1[q]);
        g_red[b] = m1;
        __threadfence();
        is_last = (atomicAdd(&g_cnt, 1) == BATCH - 1);
    }
    __syncthreads();

    if (is_last) {
        float cm = fmaxf(0.f, MARGIN + fdec(g_cmax[t]) - g_diag[t]);
        __shared__ float sm[BATCH];
        sm[t] = g_red[t] + cm;
        g_cmax[t] = 0u;
        __syncthreads();
        #pragma unroll
        for (int o = 128; o > 0; o >>= 1) {
            if (t < o) sm[t] += sm[t + o];
            __syncthreads();
        }
        if (t == 0) { out[0] = sm[0]; g_cnt = 0; }
    }
}

// ============================================================================
extern "C" void kernel_launch(void* const* d_in, const int* in_sizes, int n_in,
                              void* d_out, int out_size)
{
    const float* im_set = (const float*)d_in[0];
    const float* s_seq  = (const float*)d_in[1];
    const int*   im_len = (const int*)d_in[2];
    const int*   s_len  = (const int*)d_in[3];
    float* out = (float*)d_out;

    cudaFuncSetAttribute(gemm_kernel, cudaFuncAttributeMaxDynamicSharedMemorySize,
                         SMEM_SZ);

    norm_kernel<<<(TROWS + 7) / 8, 256>>>(im_set, s_seq);

    dim3 grid(NCOLS / BN, MROWS / BM);   // (60, 72)
    gemm_kernel<<<grid, NTH, SMEM_SZ>>>(im_len);

    scoreloss_kernel<<<BATCH, 256>>>(im_len, s_len, out);
}